// round 10
// baseline (speedup 1.0000x reference)
#include <cuda_runtime.h>
#include <cuda_bf16.h>
#include <cuda_fp16.h>
#include <cstdint>

// ---------------------------------------------------------------------------
// GraphSAGE: out = normalize( [x | segsum(vals * x[cols])] @ W^T + b )
// N=100000, E=1600000, IN_F=OUT_F=128, rows sorted.
//
//   K1: prep — x -> fp16 copy + W fp16 image + row_start init (merged).
//   K1b: rowidx — CSR row_start gap-fill from sorted rows.
//   K2: SpMM — warp-per-row, fp32 gather, 4-way edge unroll / 4 accumulators
//       (MLP 2 -> 4; round-9 profile showed L2-latency-bound at MLP 2).
//   K3: fp16 HMMA GEMM, W resident in smem, A via cp.async double buffer,
//       2 CTAs/SM, fused bias + row L2-normalize.
// ---------------------------------------------------------------------------

#define NNODES   100000
#define INF      128
#define TWOK     256
#define OUTF     128

__device__ __half g_xh[(size_t)NNODES * INF];
__device__ __half g_nh[(size_t)NNODES * INF];
__device__ int    g_rowstart[NNODES + 1];
__device__ __align__(128) unsigned char g_Wh_img[65536];

// ---------------------------------------------------------------------------
// helpers
// ---------------------------------------------------------------------------
__device__ __forceinline__ uint32_t smem_u32(const void* p) {
    uint32_t a;
    asm("{ .reg .u64 t; cvta.to.shared.u64 t, %1; cvt.u32.u64 %0, t; }"
        : "=r"(a) : "l"(p));
    return a;
}
__device__ __forceinline__ uint32_t sw128(uint32_t off) {
    return off ^ ((off >> 3) & 0x70);
}
__device__ __forceinline__ void ldsm_x4(uint32_t& r0, uint32_t& r1,
                                        uint32_t& r2, uint32_t& r3, uint32_t a) {
    asm volatile("ldmatrix.sync.aligned.m8n8.x4.shared.b16 {%0,%1,%2,%3}, [%4];"
                 : "=r"(r0), "=r"(r1), "=r"(r2), "=r"(r3) : "r"(a));
}
__device__ __forceinline__ void mma_f16(float* c, const uint32_t* a,
                                        const uint32_t* b) {
    asm volatile(
        "mma.sync.aligned.m16n8k16.row.col.f32.f16.f16.f32 "
        "{%0,%1,%2,%3}, {%4,%5,%6,%7}, {%8,%9}, {%0,%1,%2,%3};"
        : "+f"(c[0]), "+f"(c[1]), "+f"(c[2]), "+f"(c[3])
        : "r"(a[0]), "r"(a[1]), "r"(a[2]), "r"(a[3]), "r"(b[0]), "r"(b[1]));
}
#define CP_ASYNC16(dst, src) \
    asm volatile("cp.async.cg.shared.global [%0], [%1], 16;" :: "r"(dst), "l"(src))
#define CP_ASYNC16Z(dst, src, sz) \
    asm volatile("cp.async.cg.shared.global [%0], [%1], 16, %2;" \
                 :: "r"(dst), "l"(src), "r"(sz))
#define CP_COMMIT() asm volatile("cp.async.commit_group;" ::: "memory")
#define CP_WAIT1()  asm volatile("cp.async.wait_group 1;" ::: "memory")
#define CP_WAIT0()  asm volatile("cp.async.wait_group 0;" ::: "memory")

// ---------------------------------------------------------------------------
// K1: x -> fp16 copy + W fp16 image + row_start init (merged).
// ---------------------------------------------------------------------------
__global__ void prep_kernel(const float* __restrict__ x,
                            const float* __restrict__ W,
                            int nc8, int E, int N) {
    int i = blockIdx.x * blockDim.x + threadIdx.x;
    if (i < nc8) {
        float4 a = reinterpret_cast<const float4*>(x)[i * 2];
        float4 b = reinterpret_cast<const float4*>(x)[i * 2 + 1];
        __half2 h0 = __floats2half2_rn(a.x, a.y);
        __half2 h1 = __floats2half2_rn(a.z, a.w);
        __half2 h2 = __floats2half2_rn(b.x, b.y);
        __half2 h3 = __floats2half2_rn(b.z, b.w);
        uint4 o;
        o.x = *reinterpret_cast<uint32_t*>(&h0);
        o.y = *reinterpret_cast<uint32_t*>(&h1);
        o.z = *reinterpret_cast<uint32_t*>(&h2);
        o.w = *reinterpret_cast<uint32_t*>(&h3);
        reinterpret_cast<uint4*>(g_xh)[i] = o;
    }
    if (i <= N) g_rowstart[i] = E;
    if (i < 8192) {                     // W image: 8192 float4s
        int row   = i >> 6;
        int kf    = i & 63;
        int chunk = kf >> 4;
        int k4    = kf & 15;
        float4 wv = *reinterpret_cast<const float4*>(W + row * TWOK + chunk * 64 + k4 * 4);
        __half2 h0 = __floats2half2_rn(wv.x, wv.y);
        __half2 h1 = __floats2half2_rn(wv.z, wv.w);
        uint32_t off = chunk * 16384 + sw128((uint32_t)(row * 128 + k4 * 8));
        *reinterpret_cast<uint2*>(g_Wh_img + off) =
            make_uint2(*reinterpret_cast<uint32_t*>(&h0),
                       *reinterpret_cast<uint32_t*>(&h1));
    }
}

// ---------------------------------------------------------------------------
// K1b: CSR gap-fill from sorted rows.
// ---------------------------------------------------------------------------
__global__ void rowidx_kernel(const int* __restrict__ rows, int E) {
    int e = blockIdx.x * blockDim.x + threadIdx.x;
    if (e >= E) return;
    int r = __ldg(rows + e);
    int prev = (e == 0) ? -1 : __ldg(rows + e - 1);
    if (r != prev) {
        for (int q = prev + 1; q <= r; q++) g_rowstart[q] = e;
    }
}

// ---------------------------------------------------------------------------
// K2: SpMM, warp per row, fp32 gather, 4-way unroll / 4 accumulators.
// ---------------------------------------------------------------------------
__global__ void spmm_kernel(const float* __restrict__ x,
                            const int*   __restrict__ cols,
                            const float* __restrict__ vals,
                            int N) {
    int warp = (blockIdx.x * blockDim.x + threadIdx.x) >> 5;
    int lane = threadIdx.x & 31;
    if (warp >= N) return;
    int row = warp;

    int s  = __ldg(g_rowstart + row);
    int en = __ldg(g_rowstart + row + 1);

    const float4* x4 = reinterpret_cast<const float4*>(x);
    float4 a0 = make_float4(0.f, 0.f, 0.f, 0.f);
    float4 a1 = make_float4(0.f, 0.f, 0.f, 0.f);
    float4 a2 = make_float4(0.f, 0.f, 0.f, 0.f);
    float4 a3 = make_float4(0.f, 0.f, 0.f, 0.f);

    for (int e0 = s; e0 < en; e0 += 32) {
        int   idx = e0 + lane;
        bool  vd  = idx < en;
        int   c0  = vd ? __ldg(cols + idx) : 0;
        float v0  = vd ? __ldg(vals + idx) : 0.f;
        int n = min(32, en - e0);
        int j = 0;
        for (; j + 3 < n; j += 4) {
            int   ca = __shfl_sync(0xffffffffu, c0, j);
            int   cb = __shfl_sync(0xffffffffu, c0, j + 1);
            int   cc = __shfl_sync(0xffffffffu, c0, j + 2);
            int   cd = __shfl_sync(0xffffffffu, c0, j + 3);
            float va = __shfl_sync(0xffffffffu, v0, j);
            float vb = __shfl_sync(0xffffffffu, v0, j + 1);
            float vc = __shfl_sync(0xffffffffu, v0, j + 2);
            float vdv = __shfl_sync(0xffffffffu, v0, j + 3);
            float4 xa = x4[(size_t)ca * 32 + lane];
            float4 xb = x4[(size_t)cb * 32 + lane];
            float4 xc = x4[(size_t)cc * 32 + lane];
            float4 xd = x4[(size_t)cd * 32 + lane];
            a0.x = fmaf(va, xa.x, a0.x);  a0.y = fmaf(va, xa.y, a0.y);
            a0.z = fmaf(va, xa.z, a0.z);  a0.w = fmaf(va, xa.w, a0.w);
            a1.x = fmaf(vb, xb.x, a1.x);  a1.y = fmaf(vb, xb.y, a1.y);
            a1.z = fmaf(vb, xb.z, a1.z);  a1.w = fmaf(vb, xb.w, a1.w);
            a2.x = fmaf(vc, xc.x, a2.x);  a2.y = fmaf(vc, xc.y, a2.y);
            a2.z = fmaf(vc, xc.z, a2.z);  a2.w = fmaf(vc, xc.w, a2.w);
            a3.x = fmaf(vdv, xd.x, a3.x); a3.y = fmaf(vdv, xd.y, a3.y);
            a3.z = fmaf(vdv, xd.z, a3.z); a3.w = fmaf(vdv, xd.w, a3.w);
        }
        for (; j < n; j++) {
            int   ca = __shfl_sync(0xffffffffu, c0, j);
            float va = __shfl_sync(0xffffffffu, v0, j);
            float4 xa = x4[(size_t)ca * 32 + lane];
            a0.x = fmaf(va, xa.x, a0.x);  a0.y = fmaf(va, xa.y, a0.y);
            a0.z = fmaf(va, xa.z, a0.z);  a0.w = fmaf(va, xa.w, a0.w);
        }
    }

    a0.x += a1.x + a2.x + a3.x;
    a0.y += a1.y + a2.y + a3.y;
    a0.z += a1.z + a2.z + a3.z;
    a0.w += a1.w + a2.w + a3.w;

    __half2 h0 = __floats2half2_rn(a0.x, a0.y);
    __half2 h1 = __floats2half2_rn(a0.z, a0.w);
    reinterpret_cast<uint2*>(g_nh)[(size_t)row * 32 + lane] =
        make_uint2(*reinterpret_cast<uint32_t*>(&h0),
                   *reinterpret_cast<uint32_t*>(&h1));
}

// ---------------------------------------------------------------------------
// K3: fp16 HMMA GEMM + bias + L2 normalize. (unchanged)
// ---------------------------------------------------------------------------
#define SM_W    0
#define SM_A    65536                 // 2 stages x 16384
#define SM_BIAS (SM_A + 32768)
#define SM_RSS  (SM_BIAS + 512)
#define SM_TOTAL (SM_RSS + 2048)

__global__ void __launch_bounds__(256, 2)
gemm_norm_kernel(const float* __restrict__ b,
                 float* __restrict__ out,
                 int N) {
    extern __shared__ char smem[];
    uint32_t sb = smem_u32(smem);
    float* bias = reinterpret_cast<float*>(smem + SM_BIAS);
    float (*rss)[128] = reinterpret_cast<float (*)[128]>(smem + SM_RSS);

    int t    = threadIdx.x;
    int wid  = t >> 5;
    int lane = t & 31;
    int warp_m = wid & 1;
    int warp_n = wid >> 1;
    int rowBase = blockIdx.x * 128;

    #pragma unroll
    for (int j = 0; j < 16; j++)
        CP_ASYNC16(sb + SM_W + t * 16 + j * 4096, g_Wh_img + t * 16 + j * 4096);

    const char* xb = reinterpret_cast<const char*>(g_xh);
    const char* nb = reinterpret_cast<const char*>(g_nh);

    auto stageA = [&](int c) {
        const char* srcb = (c < 2) ? (xb + c * 128) : (nb + (c - 2) * 128);
        uint32_t dstb = sb + SM_A + (c & 1) * 16384;
        #pragma unroll
        for (int j = 0; j < 4; j++) {
            int i  = t + 256 * j;
            int r  = i >> 3;
            int u8 = i & 7;
            int gr = rowBase + r;
            uint32_t sz = (gr < N) ? 16u : 0u;
            CP_ASYNC16Z(dstb + sw128((uint32_t)(r * 128 + u8 * 16)),
                        srcb + (size_t)gr * 256 + u8 * 16, sz);
        }
    };

    stageA(0); CP_COMMIT();
    stageA(1); CP_COMMIT();

    if (t < OUTF) bias[t] = __ldg(b + t);

    float acc[4][4][4];
    #pragma unroll
    for (int mi = 0; mi < 4; mi++)
        #pragma unroll
        for (int ni = 0; ni < 4; ni++)
            #pragma unroll
            for (int r = 0; r < 4; r++) acc[mi][ni][r] = 0.f;

    int aRow  = warp_m * 64 + (lane & 15);
    int aK8   = (lane >> 4) * 8;
    int bRowX = warp_n * 32 + (lane & 7) + ((lane >> 4) & 1) * 8;
    int bK8   = ((lane >> 3) & 1) * 8;

    #pragma unroll
    for (int c = 0; c < 4; c++) {
        if (c < 3) { CP_WAIT1(); } else { CP_WAIT0(); }
        __syncthreads();

        uint32_t aBuf  = sb + SM_A + (c & 1) * 16384;
        uint32_t wBase = sb + SM_W + c * 16384;
        #pragma unroll
        for (int kk = 0; kk < 64; kk += 16) {
            uint32_t a[4][4], bb[4][2];
            #pragma unroll
            for (int mi = 0; mi < 4; mi++) {
                uint32_t off = sw128((uint32_t)((aRow + mi * 16) * 128
                                                + (kk + aK8) * 2));
                ldsm_x4(a[mi][0], a[mi][1], a[mi][2], a[mi][3], aBuf + off);
            }
            #pragma unroll
            for (int p = 0; p < 2; p++) {
                uint32_t off = sw128((uint32_t)((bRowX + p * 16) * 128
                                                + (kk + bK8) * 2));
                ldsm_x4(bb[2*p][0], bb[2*p][1], bb[2*p+1][0], bb[2*p+1][1],
                        wBase + off);
            }
            #pragma unroll
            for (int mi = 0; mi < 4; mi++)
                #pragma unroll
                for (int ni = 0; ni < 4; ni++)
                    mma_f16(acc[mi][ni], a[mi], bb[ni]);
        }

        if (c < 2) {
            __syncthreads();
            stageA(c + 2); CP_COMMIT();
        }
    }

    // ---- epilogue ----
    int colBase = warp_n * 32 + 2 * (lane & 3);
    #pragma unroll
    for (int mi = 0; mi < 4; mi++)
        #pragma unroll
        for (int ni = 0; ni < 4; ni++) {
            float b0 = bias[colBase + ni * 8];
            float b1 = bias[colBase + ni * 8 + 1];
            acc[mi][ni][0] += b0;  acc[mi][ni][1] += b1;
            acc[mi][ni][2] += b0;  acc[mi][ni][3] += b1;
        }

    #pragma unroll
    for (int mi = 0; mi < 4; mi++) {
        #pragma unroll
        for (int half = 0; half < 2; half++) {
            float s = 0.f;
            #pragma unroll
            for (int ni = 0; ni < 4; ni++) {
                float c0 = acc[mi][ni][half * 2 + 0];
                float c1 = acc[mi][ni][half * 2 + 1];
                s = fmaf(c0, c0, s);
                s = fmaf(c1, c1, s);
            }
            s += __shfl_xor_sync(0xffffffffu, s, 1);
            s += __shfl_xor_sync(0xffffffffu, s, 2);
            if ((lane & 3) == 0)
                rss[warp_n][warp_m * 64 + mi * 16 + half * 8 + (lane >> 2)] = s;
        }
    }
    __syncthreads();

    float2* out2 = reinterpret_cast<float2*>(out);
    #pragma unroll
    for (int mi = 0; mi < 4; mi++) {
        #pragma unroll
        for (int half = 0; half < 2; half++) {
            int rl  = warp_m * 64 + mi * 16 + half * 8 + (lane >> 2);
            int row = rowBase + rl;
            if (row < N) {
                float ss = rss[0][rl] + rss[1][rl] + rss[2][rl] + rss[3][rl];
                float scale = 1.f / fmaxf(sqrtf(ss), 1e-12f);
                #pragma unroll
                for (int ni = 0; ni < 4; ni++) {
                    float2 o;
                    o.x = acc[mi][ni][half * 2 + 0] * scale;
                    o.y = acc[mi][ni][half * 2 + 1] * scale;
                    out2[(size_t)row * 64 + (colBase + ni * 8) / 2] = o;
                }
            }
        }
    }
}

// ---------------------------------------------------------------------------
// Launch
// ---------------------------------------------------------------------------
extern "C" void kernel_launch(void* const* d_in, const int* in_sizes, int n_in,
                              void* d_out, int out_size) {
    const float* x    = (const float*)d_in[0];
    const int*   rows = (const int*)  d_in[1];
    const int*   cols = (const int*)  d_in[2];
    const float* vals = (const float*)d_in[3];
    const float* W    = (const float*)d_in[4];
    const float* b    = (const float*)d_in[5];
    float*       out  = (float*)d_out;

    int N = in_sizes[0] / INF;
    int E = in_sizes[1];

    cudaFuncSetAttribute(gemm_norm_kernel,
                         cudaFuncAttributeMaxDynamicSharedMemorySize, SM_TOTAL);

    // K1: x fp16 + W image + row_start init
    int nc8 = N * (INF / 8);
    prep_kernel<<<(nc8 + 255) / 256, 256>>>(x, W, nc8, E, N);

    // K1b: CSR row_start gap-fill
    rowidx_kernel<<<(E + 255) / 256, 256>>>(rows, E);

    // K2: SpMM (warp per row, fp32 gather, MLP 4)
    int blocks = (N * 32 + 255) / 256;
    spmm_kernel<<<blocks, 256>>>(x, cols, vals, N);

    // K3: fp16 HMMA GEMM + bias + normalize
    gemm_norm_kernel<<<(N + 127) / 128, 256, SM_TOTAL>>>(b, out, N);
}

// round 11
// speedup vs baseline: 1.0057x; 1.0057x over previous
#include <cuda_runtime.h>
#include <cuda_bf16.h>
#include <cuda_fp16.h>
#include <cstdint>

// ---------------------------------------------------------------------------
// GraphSAGE: out = normalize( [x | segsum(vals * x[cols])] @ W^T + b )
// N=100000, E=1600000, IN_F=OUT_F=128, rows sorted.
//
//   K1: prep — x -> fp16 copy + W fp16 image + row_start init (merged).
//   K1b: rowidx — CSR row_start gap-fill from sorted rows.
//   K2: SpMM — warp-per-row, NO shfl (broadcast __ldg of warp-uniform edge
//       metadata), 4 independent gathers in flight, per-lane base pointer.
//   K3: fp16 HMMA GEMM, W resident in smem, A via cp.async double buffer,
//       2 CTAs/SM, fused bias + row L2-normalize.
// ---------------------------------------------------------------------------

#define NNODES   100000
#define INF      128
#define TWOK     256
#define OUTF     128

__device__ __half g_xh[(size_t)NNODES * INF];
__device__ __half g_nh[(size_t)NNODES * INF];
__device__ int    g_rowstart[NNODES + 1];
__device__ __align__(128) unsigned char g_Wh_img[65536];

// ---------------------------------------------------------------------------
// helpers
// ---------------------------------------------------------------------------
__device__ __forceinline__ uint32_t smem_u32(const void* p) {
    uint32_t a;
    asm("{ .reg .u64 t; cvta.to.shared.u64 t, %1; cvt.u32.u64 %0, t; }"
        : "=r"(a) : "l"(p));
    return a;
}
__device__ __forceinline__ uint32_t sw128(uint32_t off) {
    return off ^ ((off >> 3) & 0x70);
}
__device__ __forceinline__ void ldsm_x4(uint32_t& r0, uint32_t& r1,
                                        uint32_t& r2, uint32_t& r3, uint32_t a) {
    asm volatile("ldmatrix.sync.aligned.m8n8.x4.shared.b16 {%0,%1,%2,%3}, [%4];"
                 : "=r"(r0), "=r"(r1), "=r"(r2), "=r"(r3) : "r"(a));
}
__device__ __forceinline__ void mma_f16(float* c, const uint32_t* a,
                                        const uint32_t* b) {
    asm volatile(
        "mma.sync.aligned.m16n8k16.row.col.f32.f16.f16.f32 "
        "{%0,%1,%2,%3}, {%4,%5,%6,%7}, {%8,%9}, {%0,%1,%2,%3};"
        : "+f"(c[0]), "+f"(c[1]), "+f"(c[2]), "+f"(c[3])
        : "r"(a[0]), "r"(a[1]), "r"(a[2]), "r"(a[3]), "r"(b[0]), "r"(b[1]));
}
#define CP_ASYNC16(dst, src) \
    asm volatile("cp.async.cg.shared.global [%0], [%1], 16;" :: "r"(dst), "l"(src))
#define CP_ASYNC16Z(dst, src, sz) \
    asm volatile("cp.async.cg.shared.global [%0], [%1], 16, %2;" \
                 :: "r"(dst), "l"(src), "r"(sz))
#define CP_COMMIT() asm volatile("cp.async.commit_group;" ::: "memory")
#define CP_WAIT1()  asm volatile("cp.async.wait_group 1;" ::: "memory")
#define CP_WAIT0()  asm volatile("cp.async.wait_group 0;" ::: "memory")

// ---------------------------------------------------------------------------
// K1: x -> fp16 copy + W fp16 image + row_start init (merged).
// ---------------------------------------------------------------------------
__global__ void prep_kernel(const float* __restrict__ x,
                            const float* __restrict__ W,
                            int nc8, int E, int N) {
    int i = blockIdx.x * blockDim.x + threadIdx.x;
    if (i < nc8) {
        float4 a = reinterpret_cast<const float4*>(x)[i * 2];
        float4 b = reinterpret_cast<const float4*>(x)[i * 2 + 1];
        __half2 h0 = __floats2half2_rn(a.x, a.y);
        __half2 h1 = __floats2half2_rn(a.z, a.w);
        __half2 h2 = __floats2half2_rn(b.x, b.y);
        __half2 h3 = __floats2half2_rn(b.z, b.w);
        uint4 o;
        o.x = *reinterpret_cast<uint32_t*>(&h0);
        o.y = *reinterpret_cast<uint32_t*>(&h1);
        o.z = *reinterpret_cast<uint32_t*>(&h2);
        o.w = *reinterpret_cast<uint32_t*>(&h3);
        reinterpret_cast<uint4*>(g_xh)[i] = o;
    }
    if (i <= N) g_rowstart[i] = E;
    if (i < 8192) {                     // W image: 8192 float4s
        int row   = i >> 6;
        int kf    = i & 63;
        int chunk = kf >> 4;
        int k4    = kf & 15;
        float4 wv = *reinterpret_cast<const float4*>(W + row * TWOK + chunk * 64 + k4 * 4);
        __half2 h0 = __floats2half2_rn(wv.x, wv.y);
        __half2 h1 = __floats2half2_rn(wv.z, wv.w);
        uint32_t off = chunk * 16384 + sw128((uint32_t)(row * 128 + k4 * 8));
        *reinterpret_cast<uint2*>(g_Wh_img + off) =
            make_uint2(*reinterpret_cast<uint32_t*>(&h0),
                       *reinterpret_cast<uint32_t*>(&h1));
    }
}

// ---------------------------------------------------------------------------
// K1b: CSR gap-fill from sorted rows.
// ---------------------------------------------------------------------------
__global__ void rowidx_kernel(const int* __restrict__ rows, int E) {
    int e = blockIdx.x * blockDim.x + threadIdx.x;
    if (e >= E) return;
    int r = __ldg(rows + e);
    int prev = (e == 0) ? -1 : __ldg(rows + e - 1);
    if (r != prev) {
        for (int q = prev + 1; q <= r; q++) g_rowstart[q] = e;
    }
}

// ---------------------------------------------------------------------------
// K2: SpMM, warp per row, fp32 gather, no shfl.
// Edge metadata read via warp-uniform broadcast __ldg (L1 hit, LSU pipe).
// 4 independent gathers + 4 accumulators per step.
// ---------------------------------------------------------------------------
__global__ void spmm_kernel(const float* __restrict__ x,
                            const int*   __restrict__ cols,
                            const float* __restrict__ vals,
                            int N) {
    int warp = (blockIdx.x * blockDim.x + threadIdx.x) >> 5;
    int lane = threadIdx.x & 31;
    if (warp >= N) return;

    int s  = __ldg(g_rowstart + warp);
    int en = __ldg(g_rowstart + warp + 1);

    const float* xl = x + lane * 4;          // per-lane base: dims [4l,4l+4)

    float4 a0 = make_float4(0.f, 0.f, 0.f, 0.f);
    float4 a1 = make_float4(0.f, 0.f, 0.f, 0.f);
    float4 a2 = make_float4(0.f, 0.f, 0.f, 0.f);
    float4 a3 = make_float4(0.f, 0.f, 0.f, 0.f);

    int e = s;
    for (; e + 3 < en; e += 4) {
        int   c0 = __ldg(cols + e);
        int   c1 = __ldg(cols + e + 1);
        int   c2 = __ldg(cols + e + 2);
        int   c3 = __ldg(cols + e + 3);
        float v0 = __ldg(vals + e);
        float v1 = __ldg(vals + e + 1);
        float v2 = __ldg(vals + e + 2);
        float v3 = __ldg(vals + e + 3);
        float4 x0 = *reinterpret_cast<const float4*>(xl + (size_t)c0 * INF);
        float4 x1 = *reinterpret_cast<const float4*>(xl + (size_t)c1 * INF);
        float4 x2 = *reinterpret_cast<const float4*>(xl + (size_t)c2 * INF);
        float4 x3 = *reinterpret_cast<const float4*>(xl + (size_t)c3 * INF);
        a0.x = fmaf(v0, x0.x, a0.x);  a0.y = fmaf(v0, x0.y, a0.y);
        a0.z = fmaf(v0, x0.z, a0.z);  a0.w = fmaf(v0, x0.w, a0.w);
        a1.x = fmaf(v1, x1.x, a1.x);  a1.y = fmaf(v1, x1.y, a1.y);
        a1.z = fmaf(v1, x1.z, a1.z);  a1.w = fmaf(v1, x1.w, a1.w);
        a2.x = fmaf(v2, x2.x, a2.x);  a2.y = fmaf(v2, x2.y, a2.y);
        a2.z = fmaf(v2, x2.z, a2.z);  a2.w = fmaf(v2, x2.w, a2.w);
        a3.x = fmaf(v3, x3.x, a3.x);  a3.y = fmaf(v3, x3.y, a3.y);
        a3.z = fmaf(v3, x3.z, a3.z);  a3.w = fmaf(v3, x3.w, a3.w);
    }
    for (; e < en; e++) {
        int   c0 = __ldg(cols + e);
        float v0 = __ldg(vals + e);
        float4 x0 = *reinterpret_cast<const float4*>(xl + (size_t)c0 * INF);
        a0.x = fmaf(v0, x0.x, a0.x);  a0.y = fmaf(v0, x0.y, a0.y);
        a0.z = fmaf(v0, x0.z, a0.z);  a0.w = fmaf(v0, x0.w, a0.w);
    }

    a0.x += a1.x + a2.x + a3.x;
    a0.y += a1.y + a2.y + a3.y;
    a0.z += a1.z + a2.z + a3.z;
    a0.w += a1.w + a2.w + a3.w;

    __half2 h0 = __floats2half2_rn(a0.x, a0.y);
    __half2 h1 = __floats2half2_rn(a0.z, a0.w);
    reinterpret_cast<uint2*>(g_nh)[(size_t)warp * 32 + lane] =
        make_uint2(*reinterpret_cast<uint32_t*>(&h0),
                   *reinterpret_cast<uint32_t*>(&h1));
}

// ---------------------------------------------------------------------------
// K3: fp16 HMMA GEMM + bias + L2 normalize. (unchanged)
// ---------------------------------------------------------------------------
#define SM_W    0
#define SM_A    65536                 // 2 stages x 16384
#define SM_BIAS (SM_A + 32768)
#define SM_RSS  (SM_BIAS + 512)
#define SM_TOTAL (SM_RSS + 2048)

__global__ void __launch_bounds__(256, 2)
gemm_norm_kernel(const float* __restrict__ b,
                 float* __restrict__ out,
                 int N) {
    extern __shared__ char smem[];
    uint32_t sb = smem_u32(smem);
    float* bias = reinterpret_cast<float*>(smem + SM_BIAS);
    float (*rss)[128] = reinterpret_cast<float (*)[128]>(smem + SM_RSS);

    int t    = threadIdx.x;
    int wid  = t >> 5;
    int lane = t & 31;
    int warp_m = wid & 1;
    int warp_n = wid >> 1;
    int rowBase = blockIdx.x * 128;

    #pragma unroll
    for (int j = 0; j < 16; j++)
        CP_ASYNC16(sb + SM_W + t * 16 + j * 4096, g_Wh_img + t * 16 + j * 4096);

    const char* xb = reinterpret_cast<const char*>(g_xh);
    const char* nb = reinterpret_cast<const char*>(g_nh);

    auto stageA = [&](int c) {
        const char* srcb = (c < 2) ? (xb + c * 128) : (nb + (c - 2) * 128);
        uint32_t dstb = sb + SM_A + (c & 1) * 16384;
        #pragma unroll
        for (int j = 0; j < 4; j++) {
            int i  = t + 256 * j;
            int r  = i >> 3;
            int u8 = i & 7;
            int gr = rowBase + r;
            uint32_t sz = (gr < N) ? 16u : 0u;
            CP_ASYNC16Z(dstb + sw128((uint32_t)(r * 128 + u8 * 16)),
                        srcb + (size_t)gr * 256 + u8 * 16, sz);
        }
    };

    stageA(0); CP_COMMIT();
    stageA(1); CP_COMMIT();

    if (t < OUTF) bias[t] = __ldg(b + t);

    float acc[4][4][4];
    #pragma unroll
    for (int mi = 0; mi < 4; mi++)
        #pragma unroll
        for (int ni = 0; ni < 4; ni++)
            #pragma unroll
            for (int r = 0; r < 4; r++) acc[mi][ni][r] = 0.f;

    int aRow  = warp_m * 64 + (lane & 15);
    int aK8   = (lane >> 4) * 8;
    int bRowX = warp_n * 32 + (lane & 7) + ((lane >> 4) & 1) * 8;
    int bK8   = ((lane >> 3) & 1) * 8;

    #pragma unroll
    for (int c = 0; c < 4; c++) {
        if (c < 3) { CP_WAIT1(); } else { CP_WAIT0(); }
        __syncthreads();

        uint32_t aBuf  = sb + SM_A + (c & 1) * 16384;
        uint32_t wBase = sb + SM_W + c * 16384;
        #pragma unroll
        for (int kk = 0; kk < 64; kk += 16) {
            uint32_t a[4][4], bb[4][2];
            #pragma unroll
            for (int mi = 0; mi < 4; mi++) {
                uint32_t off = sw128((uint32_t)((aRow + mi * 16) * 128
                                                + (kk + aK8) * 2));
                ldsm_x4(a[mi][0], a[mi][1], a[mi][2], a[mi][3], aBuf + off);
            }
            #pragma unroll
            for (int p = 0; p < 2; p++) {
                uint32_t off = sw128((uint32_t)((bRowX + p * 16) * 128
                                                + (kk + bK8) * 2));
                ldsm_x4(bb[2*p][0], bb[2*p][1], bb[2*p+1][0], bb[2*p+1][1],
                        wBase + off);
            }
            #pragma unroll
            for (int mi = 0; mi < 4; mi++)
                #pragma unroll
                for (int ni = 0; ni < 4; ni++)
                    mma_f16(acc[mi][ni], a[mi], bb[ni]);
        }

        if (c < 2) {
            __syncthreads();
            stageA(c + 2); CP_COMMIT();
        }
    }

    // ---- epilogue ----
    int colBase = warp_n * 32 + 2 * (lane & 3);
    #pragma unroll
    for (int mi = 0; mi < 4; mi++)
        #pragma unroll
        for (int ni = 0; ni < 4; ni++) {
            float b0 = bias[colBase + ni * 8];
            float b1 = bias[colBase + ni * 8 + 1];
            acc[mi][ni][0] += b0;  acc[mi][ni][1] += b1;
            acc[mi][ni][2] += b0;  acc[mi][ni][3] += b1;
        }

    #pragma unroll
    for (int mi = 0; mi < 4; mi++) {
        #pragma unroll
        for (int half = 0; half < 2; half++) {
            float s = 0.f;
            #pragma unroll
            for (int ni = 0; ni < 4; ni++) {
                float c0 = acc[mi][ni][half * 2 + 0];
                float c1 = acc[mi][ni][half * 2 + 1];
                s = fmaf(c0, c0, s);
                s = fmaf(c1, c1, s);
            }
            s += __shfl_xor_sync(0xffffffffu, s, 1);
            s += __shfl_xor_sync(0xffffffffu, s, 2);
            if ((lane & 3) == 0)
                rss[warp_n][warp_m * 64 + mi * 16 + half * 8 + (lane >> 2)] = s;
        }
    }
    __syncthreads();

    float2* out2 = reinterpret_cast<float2*>(out);
    #pragma unroll
    for (int mi = 0; mi < 4; mi++) {
        #pragma unroll
        for (int half = 0; half < 2; half++) {
            int rl  = warp_m * 64 + mi * 16 + half * 8 + (lane >> 2);
            int row = rowBase + rl;
            if (row < N) {
                float ss = rss[0][rl] + rss[1][rl] + rss[2][rl] + rss[3][rl];
                float scale = 1.f / fmaxf(sqrtf(ss), 1e-12f);
                #pragma unroll
                for (int ni = 0; ni < 4; ni++) {
                    float2 o;
                    o.x = acc[mi][ni][half * 2 + 0] * scale;
                    o.y = acc[mi][ni][half * 2 + 1] * scale;
                    out2[(size_t)row * 64 + (colBase + ni * 8) / 2] = o;
                }
            }
        }
    }
}

// ---------------------------------------------------------------------------
// Launch
// ---------------------------------------------------------------------------
extern "C" void kernel_launch(void* const* d_in, const int* in_sizes, int n_in,
                              void* d_out, int out_size) {
    const float* x    = (const float*)d_in[0];
    const int*   rows = (const int*)  d_in[1];
    const int*   cols = (const int*)  d_in[2];
    const float* vals = (const float*)d_in[3];
    const float* W    = (const float*)d_in[4];
    const float* b    = (const float*)d_in[5];
    float*       out  = (float*)d_out;

    int N = in_sizes[0] / INF;
    int E = in_sizes[1];

    cudaFuncSetAttribute(gemm_norm_kernel,
                         cudaFuncAttributeMaxDynamicSharedMemorySize, SM_TOTAL);

    // K1: x fp16 + W image + row_start init
    int nc8 = N * (INF / 8);
    prep_kernel<<<(nc8 + 255) / 256, 256>>>(x, W, nc8, E, N);

    // K1b: CSR row_start gap-fill
    rowidx_kernel<<<(E + 255) / 256, 256>>>(rows, E);

    // K2: SpMM (warp per row, uniform-load metadata, MLP 4)
    int blocks = (N * 32 + 255) / 256;
    spmm_kernel<<<blocks, 256>>>(x, cols, vals, N);

    // K3: fp16 HMMA GEMM + bias + normalize
    gemm_norm_kernel<<<(N + 127) / 128, 256, SM_TOTAL>>>(b, out, N);
}

// round 12
// speedup vs baseline: 1.2341x; 1.2271x over previous
#include <cuda_runtime.h>
#include <cuda_bf16.h>
#include <cuda_fp16.h>
#include <cstdint>

// ---------------------------------------------------------------------------
// GraphSAGE: out = normalize( [x | segsum(vals * x[cols])] @ W^T + b )
// N=100000, E=1600000, IN_F=OUT_F=128, rows sorted.
//
//   K1: prep — row_start init + W fp16 image (tiny; x conversion moved out).
//   K1b: rowidx — CSR row_start gap-fill from sorted rows.
//   K2: SpMM — round-9 proven body (warp-per-row, coalesced metadata +
//       2-way shfl broadcast, dual accumulators), PLUS per-row x -> fp16
//       emission (removes the 77MB prep pass).
//   K3: fp16 HMMA GEMM, W resident in smem, A via cp.async double buffer,
//       2 CTAs/SM, fused bias + row L2-normalize.
// ---------------------------------------------------------------------------

#define NNODES   100000
#define INF      128
#define TWOK     256
#define OUTF     128

__device__ __half g_xh[(size_t)NNODES * INF];
__device__ __half g_nh[(size_t)NNODES * INF];
__device__ int    g_rowstart[NNODES + 1];
__device__ __align__(128) unsigned char g_Wh_img[65536];

// ---------------------------------------------------------------------------
// helpers
// ---------------------------------------------------------------------------
__device__ __forceinline__ uint32_t smem_u32(const void* p) {
    uint32_t a;
    asm("{ .reg .u64 t; cvta.to.shared.u64 t, %1; cvt.u32.u64 %0, t; }"
        : "=r"(a) : "l"(p));
    return a;
}
__device__ __forceinline__ uint32_t sw128(uint32_t off) {
    return off ^ ((off >> 3) & 0x70);
}
__device__ __forceinline__ void ldsm_x4(uint32_t& r0, uint32_t& r1,
                                        uint32_t& r2, uint32_t& r3, uint32_t a) {
    asm volatile("ldmatrix.sync.aligned.m8n8.x4.shared.b16 {%0,%1,%2,%3}, [%4];"
                 : "=r"(r0), "=r"(r1), "=r"(r2), "=r"(r3) : "r"(a));
}
__device__ __forceinline__ void mma_f16(float* c, const uint32_t* a,
                                        const uint32_t* b) {
    asm volatile(
        "mma.sync.aligned.m16n8k16.row.col.f32.f16.f16.f32 "
        "{%0,%1,%2,%3}, {%4,%5,%6,%7}, {%8,%9}, {%0,%1,%2,%3};"
        : "+f"(c[0]), "+f"(c[1]), "+f"(c[2]), "+f"(c[3])
        : "r"(a[0]), "r"(a[1]), "r"(a[2]), "r"(a[3]), "r"(b[0]), "r"(b[1]));
}
#define CP_ASYNC16(dst, src) \
    asm volatile("cp.async.cg.shared.global [%0], [%1], 16;" :: "r"(dst), "l"(src))
#define CP_ASYNC16Z(dst, src, sz) \
    asm volatile("cp.async.cg.shared.global [%0], [%1], 16, %2;" \
                 :: "r"(dst), "l"(src), "r"(sz))
#define CP_COMMIT() asm volatile("cp.async.commit_group;" ::: "memory")
#define CP_WAIT1()  asm volatile("cp.async.wait_group 1;" ::: "memory")
#define CP_WAIT0()  asm volatile("cp.async.wait_group 0;" ::: "memory")

// ---------------------------------------------------------------------------
// K1: row_start init + W fp16 image (tiny).
// ---------------------------------------------------------------------------
__global__ void prep_kernel(const float* __restrict__ W, int E, int N) {
    int i = blockIdx.x * blockDim.x + threadIdx.x;
    if (i <= N) g_rowstart[i] = E;
    if (i < 8192) {                     // W image: 8192 float4s
        int row   = i >> 6;
        int kf    = i & 63;
        int chunk = kf >> 4;
        int k4    = kf & 15;
        float4 wv = *reinterpret_cast<const float4*>(W + row * TWOK + chunk * 64 + k4 * 4);
        __half2 h0 = __floats2half2_rn(wv.x, wv.y);
        __half2 h1 = __floats2half2_rn(wv.z, wv.w);
        uint32_t off = chunk * 16384 + sw128((uint32_t)(row * 128 + k4 * 8));
        *reinterpret_cast<uint2*>(g_Wh_img + off) =
            make_uint2(*reinterpret_cast<uint32_t*>(&h0),
                       *reinterpret_cast<uint32_t*>(&h1));
    }
}

// ---------------------------------------------------------------------------
// K1b: CSR gap-fill from sorted rows.
// ---------------------------------------------------------------------------
__global__ void rowidx_kernel(const int* __restrict__ rows, int E) {
    int e = blockIdx.x * blockDim.x + threadIdx.x;
    if (e >= E) return;
    int r = __ldg(rows + e);
    int prev = (e == 0) ? -1 : __ldg(rows + e - 1);
    if (r != prev) {
        for (int q = prev + 1; q <= r; q++) g_rowstart[q] = e;
    }
}

// ---------------------------------------------------------------------------
// K2: SpMM (round-9 proven body) + per-row x -> fp16 emission.
// Warp per row; lane owns dims [4l,4l+4). Coalesced 32-edge metadata loads,
// 2-way shfl-broadcast inner loop, dual accumulators.
// ---------------------------------------------------------------------------
__global__ void spmm_kernel(const float* __restrict__ x,
                            const int*   __restrict__ cols,
                            const float* __restrict__ vals,
                            int N) {
    int warp = (blockIdx.x * blockDim.x + threadIdx.x) >> 5;
    int lane = threadIdx.x & 31;
    if (warp >= N) return;
    int row = warp;

    int s  = __ldg(g_rowstart + row);
    int en = __ldg(g_rowstart + row + 1);

    const float4* x4 = reinterpret_cast<const float4*>(x);
    float4 acc0 = make_float4(0.f, 0.f, 0.f, 0.f);
    float4 acc1 = make_float4(0.f, 0.f, 0.f, 0.f);

    for (int e0 = s; e0 < en; e0 += 32) {
        int   idx = e0 + lane;
        bool  vd  = idx < en;
        int   c0  = vd ? __ldg(cols + idx) : 0;
        float v0  = vd ? __ldg(vals + idx) : 0.f;
        int n = min(32, en - e0);
        int j = 0;
        for (; j + 1 < n; j += 2) {
            int   cja = __shfl_sync(0xffffffffu, c0, j);
            float vja = __shfl_sync(0xffffffffu, v0, j);
            int   cjb = __shfl_sync(0xffffffffu, c0, j + 1);
            float vjb = __shfl_sync(0xffffffffu, v0, j + 1);
            float4 xa = x4[(size_t)cja * 32 + lane];
            float4 xb = x4[(size_t)cjb * 32 + lane];
            acc0.x = fmaf(vja, xa.x, acc0.x);
            acc0.y = fmaf(vja, xa.y, acc0.y);
            acc0.z = fmaf(vja, xa.z, acc0.z);
            acc0.w = fmaf(vja, xa.w, acc0.w);
            acc1.x = fmaf(vjb, xb.x, acc1.x);
            acc1.y = fmaf(vjb, xb.y, acc1.y);
            acc1.z = fmaf(vjb, xb.z, acc1.z);
            acc1.w = fmaf(vjb, xb.w, acc1.w);
        }
        if (j < n) {
            int   cja = __shfl_sync(0xffffffffu, c0, j);
            float vja = __shfl_sync(0xffffffffu, v0, j);
            float4 xa = x4[(size_t)cja * 32 + lane];
            acc0.x = fmaf(vja, xa.x, acc0.x);
            acc0.y = fmaf(vja, xa.y, acc0.y);
            acc0.z = fmaf(vja, xa.z, acc0.z);
            acc0.w = fmaf(vja, xa.w, acc0.w);
        }
    }

    acc0.x += acc1.x; acc0.y += acc1.y; acc0.z += acc1.z; acc0.w += acc1.w;

    __half2 h0 = __floats2half2_rn(acc0.x, acc0.y);
    __half2 h1 = __floats2half2_rn(acc0.z, acc0.w);
    reinterpret_cast<uint2*>(g_nh)[(size_t)row * 32 + lane] =
        make_uint2(*reinterpret_cast<uint32_t*>(&h0),
                   *reinterpret_cast<uint32_t*>(&h1));

    // x row -> fp16 (replaces the 77MB prep pass)
    float4 xr = x4[(size_t)row * 32 + lane];
    __half2 g0 = __floats2half2_rn(xr.x, xr.y);
    __half2 g1 = __floats2half2_rn(xr.z, xr.w);
    reinterpret_cast<uint2*>(g_xh)[(size_t)row * 32 + lane] =
        make_uint2(*reinterpret_cast<uint32_t*>(&g0),
                   *reinterpret_cast<uint32_t*>(&g1));
}

// ---------------------------------------------------------------------------
// K3: fp16 HMMA GEMM + bias + L2 normalize. (unchanged)
// ---------------------------------------------------------------------------
#define SM_W    0
#define SM_A    65536                 // 2 stages x 16384
#define SM_BIAS (SM_A + 32768)
#define SM_RSS  (SM_BIAS + 512)
#define SM_TOTAL (SM_RSS + 2048)

__global__ void __launch_bounds__(256, 2)
gemm_norm_kernel(const float* __restrict__ b,
                 float* __restrict__ out,
                 int N) {
    extern __shared__ char smem[];
    uint32_t sb = smem_u32(smem);
    float* bias = reinterpret_cast<float*>(smem + SM_BIAS);
    float (*rss)[128] = reinterpret_cast<float (*)[128]>(smem + SM_RSS);

    int t    = threadIdx.x;
    int wid  = t >> 5;
    int lane = t & 31;
    int warp_m = wid & 1;
    int warp_n = wid >> 1;
    int rowBase = blockIdx.x * 128;

    #pragma unroll
    for (int j = 0; j < 16; j++)
        CP_ASYNC16(sb + SM_W + t * 16 + j * 4096, g_Wh_img + t * 16 + j * 4096);

    const char* xb = reinterpret_cast<const char*>(g_xh);
    const char* nb = reinterpret_cast<const char*>(g_nh);

    auto stageA = [&](int c) {
        const char* srcb = (c < 2) ? (xb + c * 128) : (nb + (c - 2) * 128);
        uint32_t dstb = sb + SM_A + (c & 1) * 16384;
        #pragma unroll
        for (int j = 0; j < 4; j++) {
            int i  = t + 256 * j;
            int r  = i >> 3;
            int u8 = i & 7;
            int gr = rowBase + r;
            uint32_t sz = (gr < N) ? 16u : 0u;
            CP_ASYNC16Z(dstb + sw128((uint32_t)(r * 128 + u8 * 16)),
                        srcb + (size_t)gr * 256 + u8 * 16, sz);
        }
    };

    stageA(0); CP_COMMIT();
    stageA(1); CP_COMMIT();

    if (t < OUTF) bias[t] = __ldg(b + t);

    float acc[4][4][4];
    #pragma unroll
    for (int mi = 0; mi < 4; mi++)
        #pragma unroll
        for (int ni = 0; ni < 4; ni++)
            #pragma unroll
            for (int r = 0; r < 4; r++) acc[mi][ni][r] = 0.f;

    int aRow  = warp_m * 64 + (lane & 15);
    int aK8   = (lane >> 4) * 8;
    int bRowX = warp_n * 32 + (lane & 7) + ((lane >> 4) & 1) * 8;
    int bK8   = ((lane >> 3) & 1) * 8;

    #pragma unroll
    for (int c = 0; c < 4; c++) {
        if (c < 3) { CP_WAIT1(); } else { CP_WAIT0(); }
        __syncthreads();

        uint32_t aBuf  = sb + SM_A + (c & 1) * 16384;
        uint32_t wBase = sb + SM_W + c * 16384;
        #pragma unroll
        for (int kk = 0; kk < 64; kk += 16) {
            uint32_t a[4][4], bb[4][2];
            #pragma unroll
            for (int mi = 0; mi < 4; mi++) {
                uint32_t off = sw128((uint32_t)((aRow + mi * 16) * 128
                                                + (kk + aK8) * 2));
                ldsm_x4(a[mi][0], a[mi][1], a[mi][2], a[mi][3], aBuf + off);
            }
            #pragma unroll
            for (int p = 0; p < 2; p++) {
                uint32_t off = sw128((uint32_t)((bRowX + p * 16) * 128
                                                + (kk + bK8) * 2));
                ldsm_x4(bb[2*p][0], bb[2*p][1], bb[2*p+1][0], bb[2*p+1][1],
                        wBase + off);
            }
            #pragma unroll
            for (int mi = 0; mi < 4; mi++)
                #pragma unroll
                for (int ni = 0; ni < 4; ni++)
                    mma_f16(acc[mi][ni], a[mi], bb[ni]);
        }

        if (c < 2) {
            __syncthreads();
            stageA(c + 2); CP_COMMIT();
        }
    }

    // ---- epilogue ----
    int colBase = warp_n * 32 + 2 * (lane & 3);
    #pragma unroll
    for (int mi = 0; mi < 4; mi++)
        #pragma unroll
        for (int ni = 0; ni < 4; ni++) {
            float b0 = bias[colBase + ni * 8];
            float b1 = bias[colBase + ni * 8 + 1];
            acc[mi][ni][0] += b0;  acc[mi][ni][1] += b1;
            acc[mi][ni][2] += b0;  acc[mi][ni][3] += b1;
        }

    #pragma unroll
    for (int mi = 0; mi < 4; mi++) {
        #pragma unroll
        for (int half = 0; half < 2; half++) {
            float s = 0.f;
            #pragma unroll
            for (int ni = 0; ni < 4; ni++) {
                float c0 = acc[mi][ni][half * 2 + 0];
                float c1 = acc[mi][ni][half * 2 + 1];
                s = fmaf(c0, c0, s);
                s = fmaf(c1, c1, s);
            }
            s += __shfl_xor_sync(0xffffffffu, s, 1);
            s += __shfl_xor_sync(0xffffffffu, s, 2);
            if ((lane & 3) == 0)
                rss[warp_n][warp_m * 64 + mi * 16 + half * 8 + (lane >> 2)] = s;
        }
    }
    __syncthreads();

    float2* out2 = reinterpret_cast<float2*>(out);
    #pragma unroll
    for (int mi = 0; mi < 4; mi++) {
        #pragma unroll
        for (int half = 0; half < 2; half++) {
            int rl  = warp_m * 64 + mi * 16 + half * 8 + (lane >> 2);
            int row = rowBase + rl;
            if (row < N) {
                float ss = rss[0][rl] + rss[1][rl] + rss[2][rl] + rss[3][rl];
                float scale = 1.f / fmaxf(sqrtf(ss), 1e-12f);
                #pragma unroll
                for (int ni = 0; ni < 4; ni++) {
                    float2 o;
                    o.x = acc[mi][ni][half * 2 + 0] * scale;
                    o.y = acc[mi][ni][half * 2 + 1] * scale;
                    out2[(size_t)row * 64 + (colBase + ni * 8) / 2] = o;
                }
            }
        }
    }
}

// ---------------------------------------------------------------------------
// Launch
// ---------------------------------------------------------------------------
extern "C" void kernel_launch(void* const* d_in, const int* in_sizes, int n_in,
                              void* d_out, int out_size) {
    const float* x    = (const float*)d_in[0];
    const int*   rows = (const int*)  d_in[1];
    const int*   cols = (const int*)  d_in[2];
    const float* vals = (const float*)d_in[3];
    const float* W    = (const float*)d_in[4];
    const float* b    = (const float*)d_in[5];
    float*       out  = (float*)d_out;

    int N = in_sizes[0] / INF;
    int E = in_sizes[1];

    cudaFuncSetAttribute(gemm_norm_kernel,
                         cudaFuncAttributeMaxDynamicSharedMemorySize, SM_TOTAL);

    // K1: row_start init + W image (tiny)
    prep_kernel<<<(N + 256) / 256, 256>>>(W, E, N);

    // K1b: CSR row_start gap-fill
    rowidx_kernel<<<(E + 255) / 256, 256>>>(rows, E);

    // K2: SpMM (warp per row; also emits x -> fp16)
    int blocks = (N * 32 + 255) / 256;
    spmm_kernel<<<blocks, 256>>>(x, cols, vals, N);

    // K3: fp16 HMMA GEMM + bias + normalize
    gemm_norm_kernel<<<(N + 127) / 128, 256, SM_TOTAL>>>(b, out, N);
}